// round 6
// baseline (speedup 1.0000x reference)
#include <cuda_runtime.h>
#include <cuda_bf16.h>
#include <cstdint>

#define M_DIM 1024
#define N_DIM 512
#define K_DIM 512

#define BM 64
#define BN 64
#define KC 64                 // bf16 per chunk -> 128B rows (SW128)
#define NCH (K_DIM / KC)      // 8
#define NTHREADS 512
#define NSTAGE 3

// stage layout (bytes): Ahi 8K | Alo 8K | Bhi 8K | Blo 8K = 32KB
#define A_HI 0
#define A_LO 8192
#define B_HI 16384
#define B_LO 24576
#define STAGE 32768
#define SMEM_DYN (NSTAGE * STAGE)   // 96KB

// bf16 hi/lo split scratch
__device__ __align__(16) __nv_bfloat16 g_xhi[M_DIM * K_DIM];
__device__ __align__(16) __nv_bfloat16 g_xlo[M_DIM * K_DIM];
__device__ __align__(16) __nv_bfloat16 g_whi[N_DIM * K_DIM];
__device__ __align__(16) __nv_bfloat16 g_wlo[N_DIM * K_DIM];

// ---------------- helpers ----------------
__device__ __forceinline__ uint32_t smem_u32(const void* p) {
    uint32_t a;
    asm("{ .reg .u64 t; cvta.to.shared.u64 t, %1; cvt.u32.u64 %0, t; }"
        : "=r"(a) : "l"(p));
    return a;
}
__device__ __forceinline__ uint32_t sw128(uint32_t off) {
    return off ^ ((off >> 3) & 0x70);
}
__device__ __forceinline__ void cpa16(uint32_t dst, const void* src) {
    asm volatile("cp.async.cg.shared.global [%0], [%1], 16;"
                 :: "r"(dst), "l"(src));
}
__device__ __forceinline__ void ldsm4(uint32_t* r, uint32_t addr) {
    asm volatile("ldmatrix.sync.aligned.m8n8.x4.shared.b16 {%0,%1,%2,%3}, [%4];"
                 : "=r"(r[0]), "=r"(r[1]), "=r"(r[2]), "=r"(r[3]) : "r"(addr));
}
__device__ __forceinline__ void mma_bf16(float* c, const uint32_t* a, const uint32_t* b) {
    asm volatile(
        "mma.sync.aligned.m16n8k16.row.col.f32.bf16.bf16.f32 "
        "{%0,%1,%2,%3}, {%4,%5,%6,%7}, {%8,%9}, {%0,%1,%2,%3};"
        : "+f"(c[0]), "+f"(c[1]), "+f"(c[2]), "+f"(c[3])
        : "r"(a[0]), "r"(a[1]), "r"(a[2]), "r"(a[3]), "r"(b[0]), "r"(b[1]));
}

// ---------------- kernel 1: fp32 -> bf16 hi/lo split ----------------
__global__ void cvt_kernel(const float4* __restrict__ X, const float4* __restrict__ W) {
    const int NX = M_DIM * K_DIM / 4;
    int i = blockIdx.x * 256 + threadIdx.x;
    float4 v;
    uint2 *hd, *ld_;
    if (i < NX) {
        v = X[i];
        hd  = reinterpret_cast<uint2*>(g_xhi) + i;
        ld_ = reinterpret_cast<uint2*>(g_xlo) + i;
    } else {
        int j = i - NX;
        v = W[j];
        hd  = reinterpret_cast<uint2*>(g_whi) + j;
        ld_ = reinterpret_cast<uint2*>(g_wlo) + j;
    }
    __nv_bfloat16 h0 = __float2bfloat16_rn(v.x);
    __nv_bfloat16 h1 = __float2bfloat16_rn(v.y);
    __nv_bfloat16 h2 = __float2bfloat16_rn(v.z);
    __nv_bfloat16 h3 = __float2bfloat16_rn(v.w);
    __nv_bfloat16 l0 = __float2bfloat16_rn(v.x - __bfloat162float(h0));
    __nv_bfloat16 l1 = __float2bfloat16_rn(v.y - __bfloat162float(h1));
    __nv_bfloat16 l2 = __float2bfloat16_rn(v.z - __bfloat162float(h2));
    __nv_bfloat16 l3 = __float2bfloat16_rn(v.w - __bfloat162float(h3));
    __nv_bfloat162 hp0 = __halves2bfloat162(h0, h1);
    __nv_bfloat162 hp1 = __halves2bfloat162(h2, h3);
    __nv_bfloat162 lp0 = __halves2bfloat162(l0, l1);
    __nv_bfloat162 lp1 = __halves2bfloat162(l2, l3);
    uint2 hu, lu;
    hu.x = *reinterpret_cast<uint32_t*>(&hp0);
    hu.y = *reinterpret_cast<uint32_t*>(&hp1);
    lu.x = *reinterpret_cast<uint32_t*>(&lp0);
    lu.y = *reinterpret_cast<uint32_t*>(&lp1);
    *hd  = hu;
    *ld_ = lu;
}

// ---------------- kernel 2: mma.sync GEMM + fused epilogue ----------------
__global__ __launch_bounds__(NTHREADS, 1)
void gemm_kernel(const float* __restrict__ X,
                 const float* __restrict__ bias,
                 float* __restrict__ out)
{
    extern __shared__ char smem[];
    const uint32_t sbase = smem_u32(smem);

    const int tid  = threadIdx.x;
    const int lane = tid & 31;
    const int wid  = tid >> 5;           // 0..15
    const int wm   = (wid & 3) * 16;     // warp M offset (4 groups)
    const int wn   = (wid >> 2) * 16;    // warp N offset (4 groups)

    const int m0 = blockIdx.y * BM;
    const int n0 = blockIdx.x * BN;

    // three independent accumulator sets -> no serial HMMA chains
    float acc_hh[2][4], acc_hl[2][4], acc_lh[2][4];
    #pragma unroll
    for (int b = 0; b < 2; b++)
        #pragma unroll
        for (int q = 0; q < 4; q++) {
            acc_hh[b][q] = 0.0f; acc_hl[b][q] = 0.0f; acc_lh[b][q] = 0.0f;
        }

    // per-lane ldmatrix row/half precomputation
    const int arow_l  = lane & 15;                        // A m16k16 x4
    const int ahalf16 = ((lane >> 4) & 1) * 16;
    const int brow_l  = (lane & 7) + ((lane & 16) ? 8 : 0);  // B n16k16 x4
    const int bhalf16 = ((lane >> 3) & 1) * 16;

    // double-buffered fragments across k-substeps
    uint32_t fa_hi[2][4], fa_lo[2][4], fb_hi[2][4], fb_lo[2][4];

    auto load_frags = [&](uint32_t stb, int s, int pb) {
        const uint32_t kb_a = (uint32_t)(s * 32 + ahalf16);
        const uint32_t kb_b = (uint32_t)(s * 32 + bhalf16);
        const uint32_t ra = (uint32_t)(wm + arow_l);
        const uint32_t ao = ra * 128 + (kb_a ^ ((ra & 7) << 4));
        ldsm4(fa_hi[pb], stb + A_HI + ao);
        ldsm4(fa_lo[pb], stb + A_LO + ao);
        const uint32_t rb = (uint32_t)(wn + brow_l);
        const uint32_t bo = rb * 128 + (kb_b ^ ((rb & 7) << 4));
        ldsm4(fb_hi[pb], stb + B_HI + bo);
        ldsm4(fb_lo[pb], stb + B_LO + bo);
    };

    // ---- load one chunk (c) into stage st : 2048 x 16B, 4 per thread ----
    auto load_chunk = [&](int c, int st) {
        const int kc = c * KC;
        const uint32_t stb = sbase + st * STAGE;
        #pragma unroll
        for (int i = 0; i < 4; i++) {
            int u = i * NTHREADS + tid;       // 0..2047
            int region = u >> 9;              // 0=Ahi 1=Alo 2=Bhi 3=Blo
            int r  = (u >> 3) & 63;
            int cu = u & 7;
            const __nv_bfloat16* src;
            if (region == 0)      src = g_xhi + (size_t)(m0 + r) * K_DIM + kc + cu * 8;
            else if (region == 1) src = g_xlo + (size_t)(m0 + r) * K_DIM + kc + cu * 8;
            else if (region == 2) src = g_whi + (size_t)(n0 + r) * K_DIM + kc + cu * 8;
            else                  src = g_wlo + (size_t)(n0 + r) * K_DIM + kc + cu * 8;
            uint32_t dst = stb + region * 8192 + sw128((uint32_t)(r * 128 + cu * 16));
            cpa16(dst, src);
        }
        asm volatile("cp.async.commit_group;" ::: "memory");
    };

    // prologue: chunks 0,1 into stages 0,1
    load_chunk(0, 0);
    load_chunk(1, 1);

    for (int c = 0; c < NCH; c++) {
        if (c + 1 < NCH) {
            asm volatile("cp.async.wait_group 1;" ::: "memory");  // chunk c done
        } else {
            asm volatile("cp.async.wait_group 0;" ::: "memory");
        }
        __syncthreads();

        // next-next load (stage (c+2)%3 == (c-1)%3, readers all passed barrier)
        if (c + 2 < NCH) load_chunk(c + 2, (c + 2) % NSTAGE);

        const uint32_t stb = sbase + (c % NSTAGE) * STAGE;
        load_frags(stb, 0, 0);
        #pragma unroll
        for (int s = 0; s < 4; s++) {
            const int cur = s & 1;
            if (s < 3) load_frags(stb, s + 1, cur ^ 1);
            // 6 fully independent MMAs
            mma_bf16(acc_hh[0], fa_hi[cur], &fb_hi[cur][0]);
            mma_bf16(acc_hh[1], fa_hi[cur], &fb_hi[cur][2]);
            mma_bf16(acc_hl[0], fa_hi[cur], &fb_lo[cur][0]);
            mma_bf16(acc_hl[1], fa_hi[cur], &fb_lo[cur][2]);
            mma_bf16(acc_lh[0], fa_lo[cur], &fb_hi[cur][0]);
            mma_bf16(acc_lh[1], fa_lo[cur], &fb_hi[cur][2]);
        }
    }

    // ---- fused epilogue: out = x * (hh + hl + lh) + bias ----
    #pragma unroll
    for (int nt = 0; nt < 2; nt++) {
        const int m = m0 + wm + (lane >> 2);
        const int n = n0 + wn + nt * 8 + (lane & 3) * 2;
        float wx0 = acc_hh[nt][0] + (acc_hl[nt][0] + acc_lh[nt][0]);
        float wx1 = acc_hh[nt][1] + (acc_hl[nt][1] + acc_lh[nt][1]);
        float wx2 = acc_hh[nt][2] + (acc_hl[nt][2] + acc_lh[nt][2]);
        float wx3 = acc_hh[nt][3] + (acc_hl[nt][3] + acc_lh[nt][3]);
        const float2 bb = *reinterpret_cast<const float2*>(bias + n);
        const float2 x0 = *reinterpret_cast<const float2*>(X + (size_t)m * K_DIM + n);
        const float2 x1 = *reinterpret_cast<const float2*>(X + (size_t)(m + 8) * K_DIM + n);
        float2 o0, o1;
        o0.x = fmaf(x0.x, wx0, bb.x);
        o0.y = fmaf(x0.y, wx1, bb.y);
        o1.x = fmaf(x1.x, wx2, bb.x);
        o1.y = fmaf(x1.y, wx3, bb.y);
        *reinterpret_cast<float2*>(out + (size_t)m * N_DIM + n) = o0;
        *reinterpret_cast<float2*>(out + (size_t)(m + 8) * N_DIM + n) = o1;
    }
}

// ---------------- launch ----------------
extern "C" void kernel_launch(void* const* d_in, const int* in_sizes, int n_in,
                              void* d_out, int out_size) {
    const float* x    = (const float*)d_in[0];   // (1024, 512)
    const float* w    = (const float*)d_in[1];   // (512, 512)
    const float* bias = (const float*)d_in[2];   // (512,)
    float* out        = (float*)d_out;           // (1024, 512)

    cudaFuncSetAttribute(gemm_kernel, cudaFuncAttributeMaxDynamicSharedMemorySize, SMEM_DYN);

    const int total4 = (M_DIM * K_DIM + N_DIM * K_DIM) / 4;   // 196608
    cvt_kernel<<<total4 / 256, 256>>>((const float4*)x, (const float4*)w);

    dim3 grid(N_DIM / BN, M_DIM / BM);   // (8, 16) = 128 CTAs
    gemm_kernel<<<grid, NTHREADS, SMEM_DYN>>>(x, bias, out);
}

// round 7
// speedup vs baseline: 1.0175x; 1.0175x over previous
#include <cuda_runtime.h>
#include <cuda_fp16.h>
#include <cstdint>

#define M_DIM 1024
#define N_DIM 512
#define K_DIM 512

#define BM 64
#define BN 64
#define KC 64                 // fp16 per chunk -> 128B rows (SW128)
#define NCH (K_DIM / KC)      // 8
#define NTHREADS 512
#define NSTAGE 3

// stage layout (bytes): Ahi 8K | Alo 8K | Bhi 8K = 24KB
#define A_HI 0
#define A_LO 8192
#define B_HI 16384
#define STAGE 24576
#define SMEM_DYN (NSTAGE * STAGE)   // 72KB

// fp16 split scratch: x = xh + xl (exact to ~2^-22), w ~= wh (error 2^-12)
__device__ __align__(16) __half g_xhi[M_DIM * K_DIM];
__device__ __align__(16) __half g_xlo[M_DIM * K_DIM];
__device__ __align__(16) __half g_whi[N_DIM * K_DIM];

// ---------------- helpers ----------------
__device__ __forceinline__ uint32_t smem_u32(const void* p) {
    uint32_t a;
    asm("{ .reg .u64 t; cvta.to.shared.u64 t, %1; cvt.u32.u64 %0, t; }"
        : "=r"(a) : "l"(p));
    return a;
}
__device__ __forceinline__ uint32_t sw128(uint32_t off) {
    return off ^ ((off >> 3) & 0x70);
}
__device__ __forceinline__ void cpa16(uint32_t dst, const void* src) {
    asm volatile("cp.async.cg.shared.global [%0], [%1], 16;"
                 :: "r"(dst), "l"(src));
}
__device__ __forceinline__ void ldsm4(uint32_t* r, uint32_t addr) {
    asm volatile("ldmatrix.sync.aligned.m8n8.x4.shared.b16 {%0,%1,%2,%3}, [%4];"
                 : "=r"(r[0]), "=r"(r[1]), "=r"(r[2]), "=r"(r[3]) : "r"(addr));
}
__device__ __forceinline__ void mma_f16(float* c, const uint32_t* a, const uint32_t* b) {
    asm volatile(
        "mma.sync.aligned.m16n8k16.row.col.f32.f16.f16.f32 "
        "{%0,%1,%2,%3}, {%4,%5,%6,%7}, {%8,%9}, {%0,%1,%2,%3};"
        : "+f"(c[0]), "+f"(c[1]), "+f"(c[2]), "+f"(c[3])
        : "r"(a[0]), "r"(a[1]), "r"(a[2]), "r"(a[3]), "r"(b[0]), "r"(b[1]));
}

// ---------------- kernel 1: fp32 -> fp16 split ----------------
// X -> (hi, lo);  W -> hi only
__global__ void cvt_kernel(const float4* __restrict__ X, const float4* __restrict__ W) {
    const int NX = M_DIM * K_DIM / 4;
    int i = blockIdx.x * 256 + threadIdx.x;
    if (i < NX) {
        float4 v = X[i];
        __half h0 = __float2half_rn(v.x);
        __half h1 = __float2half_rn(v.y);
        __half h2 = __float2half_rn(v.z);
        __half h3 = __float2half_rn(v.w);
        __half l0 = __float2half_rn(v.x - __half2float(h0));
        __half l1 = __float2half_rn(v.y - __half2float(h1));
        __half l2 = __float2half_rn(v.z - __half2float(h2));
        __half l3 = __float2half_rn(v.w - __half2float(h3));
        __half2 hp0 = __halves2half2(h0, h1), hp1 = __halves2half2(h2, h3);
        __half2 lp0 = __halves2half2(l0, l1), lp1 = __halves2half2(l2, l3);
        uint2 hu, lu;
        hu.x = *reinterpret_cast<uint32_t*>(&hp0);
        hu.y = *reinterpret_cast<uint32_t*>(&hp1);
        lu.x = *reinterpret_cast<uint32_t*>(&lp0);
        lu.y = *reinterpret_cast<uint32_t*>(&lp1);
        *(reinterpret_cast<uint2*>(g_xhi) + i) = hu;
        *(reinterpret_cast<uint2*>(g_xlo) + i) = lu;
    } else {
        int j = i - NX;
        float4 v = W[j];
        __half2 hp0 = __halves2half2(__float2half_rn(v.x), __float2half_rn(v.y));
        __half2 hp1 = __halves2half2(__float2half_rn(v.z), __float2half_rn(v.w));
        uint2 hu;
        hu.x = *reinterpret_cast<uint32_t*>(&hp0);
        hu.y = *reinterpret_cast<uint32_t*>(&hp1);
        *(reinterpret_cast<uint2*>(g_whi) + j) = hu;
    }
}

// ---------------- kernel 2: mma.sync GEMM + fused epilogue ----------------
__global__ __launch_bounds__(NTHREADS, 1)
void gemm_kernel(const float* __restrict__ X,
                 const float* __restrict__ bias,
                 float* __restrict__ out)
{
    extern __shared__ char smem[];
    const uint32_t sbase = smem_u32(smem);

    const int tid  = threadIdx.x;
    const int lane = tid & 31;
    const int wid  = tid >> 5;           // 0..15
    const int wm   = (wid & 3) * 16;     // warp M offset (4 groups)
    const int wn   = (wid >> 2) * 16;    // warp N offset (4 groups)

    const int m0 = blockIdx.y * BM;
    const int n0 = blockIdx.x * BN;

    // two independent accumulator sets: hh = xh*wh, lh = xl*wh
    float acc_hh[2][4], acc_lh[2][4];
    #pragma unroll
    for (int b = 0; b < 2; b++)
        #pragma unroll
        for (int q = 0; q < 4; q++) { acc_hh[b][q] = 0.0f; acc_lh[b][q] = 0.0f; }

    // per-lane ldmatrix row/half precomputation
    const int arow_l  = lane & 15;
    const int ahalf16 = ((lane >> 4) & 1) * 16;
    const int brow_l  = (lane & 7) + ((lane & 16) ? 8 : 0);
    const int bhalf16 = ((lane >> 3) & 1) * 16;

    // double-buffered fragments across k-substeps
    uint32_t fa_hi[2][4], fa_lo[2][4], fb_hi[2][4];

    auto load_frags = [&](uint32_t stb, int s, int pb) {
        const uint32_t kb_a = (uint32_t)(s * 32 + ahalf16);
        const uint32_t kb_b = (uint32_t)(s * 32 + bhalf16);
        const uint32_t ra = (uint32_t)(wm + arow_l);
        const uint32_t ao = ra * 128 + (kb_a ^ ((ra & 7) << 4));
        ldsm4(fa_hi[pb], stb + A_HI + ao);
        ldsm4(fa_lo[pb], stb + A_LO + ao);
        const uint32_t rb = (uint32_t)(wn + brow_l);
        const uint32_t bo = rb * 128 + (kb_b ^ ((rb & 7) << 4));
        ldsm4(fb_hi[pb], stb + B_HI + bo);
    };

    // ---- load one chunk (c) into stage st : 1536 x 16B, 3 per thread ----
    auto load_chunk = [&](int c, int st) {
        const int kc = c * KC;
        const uint32_t stb = sbase + st * STAGE;
        #pragma unroll
        for (int i = 0; i < 3; i++) {
            int u = i * NTHREADS + tid;       // 0..1535
            int region = u >> 9;              // 0=Ahi 1=Alo 2=Bhi
            int r  = (u >> 3) & 63;
            int cu = u & 7;
            const __half* src;
            if (region == 0)      src = g_xhi + (size_t)(m0 + r) * K_DIM + kc + cu * 8;
            else if (region == 1) src = g_xlo + (size_t)(m0 + r) * K_DIM + kc + cu * 8;
            else                  src = g_whi + (size_t)(n0 + r) * K_DIM + kc + cu * 8;
            uint32_t dst = stb + region * 8192 + sw128((uint32_t)(r * 128 + cu * 16));
            cpa16(dst, src);
        }
        asm volatile("cp.async.commit_group;" ::: "memory");
    };

    // prologue: chunks 0,1 into stages 0,1
    load_chunk(0, 0);
    load_chunk(1, 1);

    for (int c = 0; c < NCH; c++) {
        if (c + 1 < NCH) {
            asm volatile("cp.async.wait_group 1;" ::: "memory");  // chunk c done
        } else {
            asm volatile("cp.async.wait_group 0;" ::: "memory");
        }
        __syncthreads();

        // next-next load (stage (c+2)%3 == (c-1)%3, readers all passed barrier)
        if (c + 2 < NCH) load_chunk(c + 2, (c + 2) % NSTAGE);

        const uint32_t stb = sbase + (c % NSTAGE) * STAGE;
        load_frags(stb, 0, 0);
        #pragma unroll
        for (int s = 0; s < 4; s++) {
            const int cur = s & 1;
            if (s < 3) load_frags(stb, s + 1, cur ^ 1);
            // 4 independent MMAs
            mma_f16(acc_hh[0], fa_hi[cur], &fb_hi[cur][0]);
            mma_f16(acc_hh[1], fa_hi[cur], &fb_hi[cur][2]);
            mma_f16(acc_lh[0], fa_lo[cur], &fb_hi[cur][0]);
            mma_f16(acc_lh[1], fa_lo[cur], &fb_hi[cur][2]);
        }
    }

    // ---- fused epilogue: out = x * (hh + lh) + bias ----
    #pragma unroll
    for (int nt = 0; nt < 2; nt++) {
        const int m = m0 + wm + (lane >> 2);
        const int n = n0 + wn + nt * 8 + (lane & 3) * 2;
        float wx0 = acc_hh[nt][0] + acc_lh[nt][0];
        float wx1 = acc_hh[nt][1] + acc_lh[nt][1];
        float wx2 = acc_hh[nt][2] + acc_lh[nt][2];
        float wx3 = acc_hh[nt][3] + acc_lh[nt][3];
        const float2 bb = *reinterpret_cast<const float2*>(bias + n);
        const float2 x0 = *reinterpret_cast<const float2*>(X + (size_t)m * K_DIM + n);
        const float2 x1 = *reinterpret_cast<const float2*>(X + (size_t)(m + 8) * K_DIM + n);
        float2 o0, o1;
        o0.x = fmaf(x0.x, wx0, bb.x);
        o0.y = fmaf(x0.y, wx1, bb.y);
        o1.x = fmaf(x1.x, wx2, bb.x);
        o1.y = fmaf(x1.y, wx3, bb.y);
        *reinterpret_cast<float2*>(out + (size_t)m * N_DIM + n) = o0;
        *reinterpret_cast<float2*>(out + (size_t)(m + 8) * N_DIM + n) = o1;
    }
}

// ---------------- launch ----------------
extern "C" void kernel_launch(void* const* d_in, const int* in_sizes, int n_in,
                              void* d_out, int out_size) {
    const float* x    = (const float*)d_in[0];   // (1024, 512)
    const float* w    = (const float*)d_in[1];   // (512, 512)
    const float* bias = (const float*)d_in[2];   // (512,)
    float* out        = (float*)d_out;           // (1024, 512)

    cudaFuncSetAttribute(gemm_kernel, cudaFuncAttributeMaxDynamicSharedMemorySize, SMEM_DYN);

    const int total4 = (M_DIM * K_DIM + N_DIM * K_DIM) / 4;   // 196608
    cvt_kernel<<<total4 / 256, 256>>>((const float4*)x, (const float4*)w);

    dim3 grid(N_DIM / BN, M_DIM / BM);   // (8, 16) = 128 CTAs
    gemm_kernel<<<grid, NTHREADS, SMEM_DYN>>>(x, bias, out);
}